// round 1
// baseline (speedup 1.0000x reference)
#include <cuda_runtime.h>
#include <cuda_bf16.h>
#include <math.h>

// ---------------- problem constants ----------------
#define BATCH 8
#define SEQ   4096
#define F_IN  586
#define DM    512
#define NH    8
#define HD    64          // head dim (D == M == 64)
#define FF    1024
#define NLAY  2
#define BS    (BATCH*SEQ) // 32768 rows
#define BH    (BATCH*NH)  // 64
#define EPS_ATTN 1e-6f
#define EPS_LN   1e-5f

// ---------------- scratch (device globals, no allocation) ----------------
__device__ float g_x [BS*DM];
__device__ float g_q [BS*DM];
__device__ float g_k [BS*DM];
__device__ float g_v [BS*DM];
__device__ float g_t [BS*DM];
__device__ float g_h [BS*FF];
#define NCHUNK 8
#define KV_CH  (SEQ/NCHUNK)   // 512 tokens per chunk
__device__ float g_kvpart[NCHUNK*BH*HD*HD];
__device__ float g_kspart[NCHUNK*BH*HD];
__device__ float g_kv[BH*HD*HD];
__device__ float g_ks[BH*HD];

// ---------------- generic SGEMM with fused epilogue ----------------
// C[M,N] = act( A[M,K] @ B[K,N] + bias[N] (+ res[M,N]) )
// act: 0 = none, 1 = elu(x)+1, 2 = relu
#define BM 128
#define BN 64
#define BK 16
#define TM 8
#define TN 4
__global__ __launch_bounds__(256) void gemm_k(
    const float* __restrict__ A, const float* __restrict__ Bw,
    const float* __restrict__ bias, const float* __restrict__ res,
    float* __restrict__ C, int M, int N, int K, int act)
{
    __shared__ float As[BK][BM];
    __shared__ float Bs[BK][BN];
    const int tid = threadIdx.x;
    const int tx = tid & 15;        // 0..15  -> column group (TN=4)
    const int ty = tid >> 4;        // 0..15  -> row group    (TM=8)
    const int rowBase = blockIdx.y * BM;
    const int colBase = blockIdx.x * BN;

    float acc[TM][TN];
#pragma unroll
    for (int i = 0; i < TM; i++)
#pragma unroll
        for (int j = 0; j < TN; j++) acc[i][j] = 0.f;

    for (int k0 = 0; k0 < K; k0 += BK) {
        // A tile: 128x16 = 2048 elems, 8/thread
#pragma unroll
        for (int i = 0; i < 8; i++) {
            int idx = tid + i * 256;
            int r = idx >> 4, c = idx & 15;
            int gc = k0 + c;
            As[c][r] = (gc < K) ? A[(size_t)(rowBase + r) * K + gc] : 0.f;
        }
        // B tile: 16x64 = 1024 elems, 4/thread (coalesced along N)
#pragma unroll
        for (int i = 0; i < 4; i++) {
            int idx = tid + i * 256;
            int r = idx >> 6, c = idx & 63;
            int gr = k0 + r;
            Bs[r][c] = (gr < K) ? Bw[(size_t)gr * N + colBase + c] : 0.f;
        }
        __syncthreads();
#pragma unroll
        for (int k = 0; k < BK; k++) {
            float4 a0 = *(const float4*)&As[k][ty * TM];
            float4 a1 = *(const float4*)&As[k][ty * TM + 4];
            float4 b0 = *(const float4*)&Bs[k][tx * TN];
            float a[TM] = {a0.x, a0.y, a0.z, a0.w, a1.x, a1.y, a1.z, a1.w};
            float b[TN] = {b0.x, b0.y, b0.z, b0.w};
#pragma unroll
            for (int i = 0; i < TM; i++)
#pragma unroll
                for (int j = 0; j < TN; j++) acc[i][j] = fmaf(a[i], b[j], acc[i][j]);
        }
        __syncthreads();
    }

#pragma unroll
    for (int i = 0; i < TM; i++) {
        int r = rowBase + ty * TM + i;
#pragma unroll
        for (int j = 0; j < TN; j++) {
            int c = colBase + tx * TN + j;
            float v = acc[i][j] + bias[c];
            if (res) v += res[(size_t)r * N + c];
            if (act == 1) v = (v > 0.f) ? (v + 1.f) : expf(v);   // elu(x)+1
            else if (act == 2) v = fmaxf(v, 0.f);
            C[(size_t)r * N + c] = v;
        }
    }
}

// ---------------- kv = sum_s k^T v  (split-S partials, deterministic) ----------------
__global__ __launch_bounds__(256) void kv_kernel(
    const float* __restrict__ k, const float* __restrict__ v,
    float* __restrict__ kvpart, float* __restrict__ kspart)
{
    const int bh = blockIdx.x;              // 0..63
    const int b = bh >> 3, h = bh & 7;
    const int chunk = blockIdx.y;           // 0..NCHUNK-1
    const int s0 = chunk * KV_CH;
    __shared__ float ksm[64][65];
    __shared__ float vsm[64][64];
    const int tid = threadIdx.x;
    const int m = tid & 63;
    const int dgrp = tid >> 6;              // 0..3
    float acc[16];
#pragma unroll
    for (int i = 0; i < 16; i++) acc[i] = 0.f;
    float kacc = 0.f;

    for (int c = 0; c < KV_CH; c += 64) {
#pragma unroll
        for (int i = 0; i < 16; i++) {
            int idx = tid + i * 256;
            int r = idx >> 6, cc = idx & 63;
            size_t gi = (size_t)(b * SEQ + s0 + c + r) * DM + h * HD + cc;
            ksm[r][cc] = k[gi];
            vsm[r][cc] = v[gi];
        }
        __syncthreads();
        for (int s = 0; s < 64; s++) {
            float vv = vsm[s][m];
#pragma unroll
            for (int i = 0; i < 16; i++)
                acc[i] = fmaf(ksm[s][dgrp * 16 + i], vv, acc[i]);
        }
        if (tid < 64) {
            float t = 0.f;
            for (int s = 0; s < 64; s++) t += ksm[s][tid];
            kacc += t;
        }
        __syncthreads();
    }
#pragma unroll
    for (int i = 0; i < 16; i++) {
        int d = dgrp * 16 + i;
        kvpart[((size_t)(chunk * BH + bh) * HD + d) * HD + m] = acc[i];
    }
    if (tid < 64) kspart[(size_t)(chunk * BH + bh) * HD + tid] = kacc;
}

__global__ void reduce_kv(const float* __restrict__ part, float* __restrict__ kv) {
    int i = blockIdx.x * 256 + threadIdx.x;            // BH*HD*HD = 262144
    float a = 0.f;
#pragma unroll
    for (int c = 0; c < NCHUNK; c++) a += part[(size_t)c * (BH * HD * HD) + i];
    kv[i] = a;
}
__global__ void reduce_ks(const float* __restrict__ part, float* __restrict__ ks) {
    int i = blockIdx.x * 256 + threadIdx.x;            // BH*HD = 4096
    float a = 0.f;
#pragma unroll
    for (int c = 0; c < NCHUNK; c++) a += part[(size_t)c * (BH * HD) + i];
    ks[i] = a;
}

// ---------------- attention apply: out = (q @ kv) * z ----------------
__global__ __launch_bounds__(256) void attn_kernel(
    const float* __restrict__ q, const float* __restrict__ kv,
    const float* __restrict__ ks, float* __restrict__ out)
{
    const int bh = blockIdx.x;
    const int b = bh >> 3, h = bh & 7;
    const int s0 = blockIdx.y * 64;
    __shared__ float kvsm[64][65];
    __shared__ float qsm[64][65];
    __shared__ float zsm[64];
    __shared__ float kssm[64];
    const int tid = threadIdx.x;
#pragma unroll
    for (int i = 0; i < 16; i++) {
        int idx = tid + i * 256;
        int d = idx >> 6, m = idx & 63;
        kvsm[d][m] = kv[((size_t)bh * HD + d) * HD + m];
        int r = d;
        qsm[r][m] = q[(size_t)(b * SEQ + s0 + r) * DM + h * HD + m];
    }
    if (tid < 64) kssm[tid] = ks[bh * HD + tid];
    __syncthreads();
    if (tid < 64) {
        float a = 0.f;
        for (int d = 0; d < 64; d++) a = fmaf(qsm[tid][d], kssm[d], a);
        zsm[tid] = 1.f / (a + EPS_ATTN);
    }
    __syncthreads();
    const int m = tid & 63;
    const int tgrp = tid >> 6;
#pragma unroll
    for (int i = 0; i < 16; i++) {
        int t = tgrp * 16 + i;
        float a = 0.f;
#pragma unroll
        for (int d = 0; d < 64; d++) a = fmaf(qsm[t][d], kvsm[d][m], a);
        out[(size_t)(b * SEQ + s0 + t) * DM + h * HD + m] = a * zsm[t];
    }
}

// ---------------- block reduce helper (128 threads) ----------------
__device__ __forceinline__ float bsum128(float v, float* sm) {
#pragma unroll
    for (int o = 16; o > 0; o >>= 1) v += __shfl_down_sync(0xffffffffu, v, o);
    int w = threadIdx.x >> 5;
    if ((threadIdx.x & 31) == 0) sm[w] = v;
    __syncthreads();
    float r = sm[0] + sm[1] + sm[2] + sm[3];
    __syncthreads();
    return r;
}

// ---------------- layernorm over DM=512 ----------------
__global__ __launch_bounds__(128) void ln_kernel(
    const float* __restrict__ in, const float* __restrict__ g,
    const float* __restrict__ b, float* __restrict__ out)
{
    __shared__ float sm[4];
    const int row = blockIdx.x;
    const int tid = threadIdx.x;
    float4 v = ((const float4*)(in + (size_t)row * DM))[tid];
    float s  = v.x + v.y + v.z + v.w;
    float sq = v.x * v.x + v.y * v.y + v.z * v.z + v.w * v.w;
    s  = bsum128(s, sm);
    sq = bsum128(sq, sm);
    float mu = s * (1.f / DM);
    float var = sq * (1.f / DM) - mu * mu;
    float rstd = rsqrtf(var + EPS_LN);
    float4 gg = ((const float4*)g)[tid];
    float4 bb = ((const float4*)b)[tid];
    float4 o;
    o.x = (v.x - mu) * rstd * gg.x + bb.x;
    o.y = (v.y - mu) * rstd * gg.y + bb.y;
    o.z = (v.z - mu) * rstd * gg.z + bb.z;
    o.w = (v.w - mu) * rstd * gg.w + bb.w;
    ((float4*)(out + (size_t)row * DM))[tid] = o;
}

// ---------------- fused final LN + output projection ----------------
__global__ __launch_bounds__(128) void final_kernel(
    const float* __restrict__ in, const float* __restrict__ g,
    const float* __restrict__ b, const float* __restrict__ w,
    const float* __restrict__ bout, float* __restrict__ out)
{
    __shared__ float sm[4];
    const int row = blockIdx.x;
    const int tid = threadIdx.x;
    float4 v = ((const float4*)(in + (size_t)row * DM))[tid];
    float s  = v.x + v.y + v.z + v.w;
    float sq = v.x * v.x + v.y * v.y + v.z * v.z + v.w * v.w;
    s  = bsum128(s, sm);
    sq = bsum128(sq, sm);
    float mu = s * (1.f / DM);
    float var = sq * (1.f / DM) - mu * mu;
    float rstd = rsqrtf(var + EPS_LN);
    float4 gg = ((const float4*)g)[tid];
    float4 bb = ((const float4*)b)[tid];
    float4 ww = ((const float4*)w)[tid];
    float acc = ((v.x - mu) * rstd * gg.x + bb.x) * ww.x
              + ((v.y - mu) * rstd * gg.y + bb.y) * ww.y
              + ((v.z - mu) * rstd * gg.z + bb.z) * ww.z
              + ((v.w - mu) * rstd * gg.w + bb.w) * ww.w;
    acc = bsum128(acc, sm);
    if (tid == 0) out[row] = acc + bout[0];
}

// ---------------- launch ----------------
static inline void launch_gemm(const float* A, const float* Bw, const float* bias,
                               const float* res, float* C, int M, int N, int K, int act) {
    dim3 grid(N / BN, M / BM);
    gemm_k<<<grid, 256>>>(A, Bw, bias, res, C, M, N, K, act);
}

extern "C" void kernel_launch(void* const* d_in, const int* in_sizes, int n_in,
                              void* d_out, int out_size)
{
    const float* emb   = (const float*)d_in[0];
    const float* W0    = (const float*)d_in[1];
    const float* b0    = (const float*)d_in[2];
    const float* Wq    = (const float*)d_in[3];
    const float* bq    = (const float*)d_in[4];
    const float* Wk    = (const float*)d_in[5];
    const float* bk    = (const float*)d_in[6];
    const float* Wv    = (const float*)d_in[7];
    const float* bv    = (const float*)d_in[8];
    const float* Wo    = (const float*)d_in[9];
    const float* bo    = (const float*)d_in[10];
    const float* ln1s  = (const float*)d_in[11];
    const float* ln1b  = (const float*)d_in[12];
    const float* W1    = (const float*)d_in[13];
    const float* b1    = (const float*)d_in[14];
    const float* W2    = (const float*)d_in[15];
    const float* b2    = (const float*)d_in[16];
    const float* ln2s  = (const float*)d_in[17];
    const float* ln2b  = (const float*)d_in[18];
    const float* lnfs  = (const float*)d_in[19];
    const float* lnfb  = (const float*)d_in[20];
    const float* Wout  = (const float*)d_in[21];
    const float* bout  = (const float*)d_in[22];
    float* out = (float*)d_out;

    float *px, *pq, *pk, *pv, *pt, *ph, *pkvp, *pksp, *pkv, *pks;
    cudaGetSymbolAddress((void**)&px,  g_x);
    cudaGetSymbolAddress((void**)&pq,  g_q);
    cudaGetSymbolAddress((void**)&pk,  g_k);
    cudaGetSymbolAddress((void**)&pv,  g_v);
    cudaGetSymbolAddress((void**)&pt,  g_t);
    cudaGetSymbolAddress((void**)&ph,  g_h);
    cudaGetSymbolAddress((void**)&pkvp, g_kvpart);
    cudaGetSymbolAddress((void**)&pksp, g_kspart);
    cudaGetSymbolAddress((void**)&pkv, g_kv);
    cudaGetSymbolAddress((void**)&pks, g_ks);

    // input projection
    launch_gemm(emb, W0, b0, nullptr, px, BS, DM, F_IN, 0);

    for (int l = 0; l < NLAY; l++) {
        const float* Wq_l = Wq + (size_t)l * DM * DM;
        const float* Wk_l = Wk + (size_t)l * DM * DM;
        const float* Wv_l = Wv + (size_t)l * DM * DM;
        const float* Wo_l = Wo + (size_t)l * DM * DM;
        const float* W1_l = W1 + (size_t)l * DM * FF;
        const float* W2_l = W2 + (size_t)l * FF * DM;
        const float* bq_l = bq + (size_t)l * DM;
        const float* bk_l = bk + (size_t)l * DM;
        const float* bv_l = bv + (size_t)l * DM;
        const float* bo_l = bo + (size_t)l * DM;
        const float* b1_l = b1 + (size_t)l * FF;
        const float* b2_l = b2 + (size_t)l * DM;

        launch_gemm(px, Wq_l, bq_l, nullptr, pq, BS, DM, DM, 1);   // elu+1
        launch_gemm(px, Wk_l, bk_l, nullptr, pk, BS, DM, DM, 1);   // elu+1
        launch_gemm(px, Wv_l, bv_l, nullptr, pv, BS, DM, DM, 0);

        kv_kernel<<<dim3(BH, NCHUNK), 256>>>(pk, pv, pkvp, pksp);
        reduce_kv<<<(BH * HD * HD) / 256, 256>>>(pkvp, pkv);
        reduce_ks<<<(BH * HD) / 256, 256>>>(pksp, pks);
        attn_kernel<<<dim3(BH, SEQ / 64), 256>>>(pq, pkv, pks, pt);

        // out-proj + residual -> pq ; LN -> px
        launch_gemm(pt, Wo_l, bo_l, px, pq, BS, DM, DM, 0);
        ln_kernel<<<BS, 128>>>(pq, ln1s + (size_t)l * DM, ln1b + (size_t)l * DM, px);

        // FFN
        launch_gemm(px, W1_l, b1_l, nullptr, ph, BS, FF, DM, 2);   // relu
        launch_gemm(ph, W2_l, b2_l, px, pq, BS, DM, FF, 0);
        ln_kernel<<<BS, 128>>>(pq, ln2s + (size_t)l * DM, ln2b + (size_t)l * DM, px);
    }

    final_kernel<<<BS, 128>>>(px, lnfs, lnfb, Wout, bout, out);
}

// round 5
// speedup vs baseline: 3.7351x; 3.7351x over previous
#include <cuda_runtime.h>
#include <cuda_bf16.h>
#include <math.h>
#include <stdint.h>

// ---------------- problem constants ----------------
#define BATCH 8
#define SEQ   4096
#define F_IN  586
#define KPAD  608            // F_IN padded to multiple of 32 (16B-aligned rows)
#define DM    512
#define NH    8
#define HD    64
#define FF    1024
#define NLAY  2
#define BS    (BATCH*SEQ) // 32768
#define BH    (BATCH*NH)  // 64
#define EPS_ATTN 1e-6f
#define EPS_LN   1e-5f

// ---------------- scratch (device globals) ----------------
__device__ float g_e [BS*KPAD];   // padded embeddings
__device__ float g_x [BS*DM];
__device__ float g_q [BS*DM];
__device__ float g_k [BS*DM];
__device__ float g_v [BS*DM];
__device__ float g_t [BS*DM];
__device__ float g_h [BS*FF];
#define NCHUNK 8
#define KV_CH  (SEQ/NCHUNK)
__device__ float g_kvpart[NCHUNK*BH*HD*HD];
__device__ float g_kspart[NCHUNK*BH*HD];
__device__ float g_kv[BH*HD*HD];
__device__ float g_ks[BH*HD];
// transposed weights [N,K]
__device__ float g_w0t[DM*KPAD];
__device__ float g_wqt[NLAY*DM*DM];
__device__ float g_wkt[NLAY*DM*DM];
__device__ float g_wvt[NLAY*DM*DM];
__device__ float g_wot[NLAY*DM*DM];
__device__ float g_w1t[NLAY*FF*DM];
__device__ float g_w2t[NLAY*DM*FF];

// ---------------- helpers ----------------
__device__ __forceinline__ uint32_t smem_u32(const void* p) {
    uint32_t a;
    asm("{ .reg .u64 t; cvta.to.shared.u64 t, %1; cvt.u32.u64 %0, t; }" : "=r"(a) : "l"(p));
    return a;
}
__device__ __forceinline__ uint32_t f2tf32(float x) {
    uint32_t r;
    asm("cvt.rna.tf32.f32 %0, %1;" : "=r"(r) : "f"(x));
    return r;
}
__device__ __forceinline__ void cp_async16(uint32_t dst, const void* src) {
    asm volatile("cp.async.cg.shared.global [%0], [%1], 16;"
                 :: "r"(dst), "l"(src) : "memory");
}
#define CP_COMMIT() asm volatile("cp.async.commit_group;" ::: "memory")

__device__ __forceinline__ void mma_tf32(float* c, const uint32_t* a, const uint32_t* b) {
    asm volatile(
        "mma.sync.aligned.m16n8k8.row.col.f32.tf32.tf32.f32 "
        "{%0,%1,%2,%3}, {%4,%5,%6,%7}, {%8,%9}, {%0,%1,%2,%3};"
        : "+f"(c[0]), "+f"(c[1]), "+f"(c[2]), "+f"(c[3])
        : "r"(a[0]), "r"(a[1]), "r"(a[2]), "r"(a[3]), "r"(b[0]), "r"(b[1]));
}

// ---------------- tensor-core tf32 GEMM ----------------
// C[M,N] = act(A[M,K] @ BT[N,K]^T + bias (+res)); K must be a multiple of 32,
// A and BT rows 16B-aligned.
#define GBM 128
#define GBN 128
#define GBK 32
#define SM_STRIDE 36                  // floats per row (bank-conflict-free pad)
#define TILE_FLOATS (128*SM_STRIDE)   // 4608 floats per tile buffer
#define GEMM_SMEM (4*TILE_FLOATS*4)   // 73728 bytes

__global__ __launch_bounds__(256) void gemm_tc(
    const float* __restrict__ A, const float* __restrict__ BT,
    const float* __restrict__ bias, const float* __restrict__ res,
    float* __restrict__ C, int M, int N, int K, int act)
{
    extern __shared__ float sm[];
    const uint32_t smBase = smem_u32(sm);
    const int tid  = threadIdx.x;
    const int warp = tid >> 5;
    const int lane = tid & 31;
    const int g = lane >> 2;          // group id 0..7
    const int t = lane & 3;           // thread-in-group 0..3
    const int warpM = warp & 3;       // 0..3
    const int warpN = warp >> 2;      // 0..1
    const int rowBase = blockIdx.y * GBM;
    const int colBase = blockIdx.x * GBN;
    const int kiters = K / GBK;

    auto aOff = [](int buf) { return buf * TILE_FLOATS; };
    auto bOff = [](int buf) { return 2 * TILE_FLOATS + buf * TILE_FLOATS; };

    const int lr = tid >> 3;          // 0..31 (row within pass)
    const int lc = tid & 7;           // 0..7  (float4 column)

    auto loadTile = [&](int it, int buf) {
        const int k0 = it * GBK;
        const int col = lc * 4;
#pragma unroll
        for (int p = 0; p < 4; p++) {
            int r = p * 32 + lr;
            uint32_t dst = smBase + (aOff(buf) + r * SM_STRIDE + col) * 4;
            cp_async16(dst, &A[(size_t)(rowBase + r) * K + k0 + col]);
        }
#pragma unroll
        for (int p = 0; p < 4; p++) {
            int r = p * 32 + lr;
            uint32_t dst = smBase + (bOff(buf) + r * SM_STRIDE + col) * 4;
            cp_async16(dst, &BT[(size_t)(colBase + r) * K + k0 + col]);
        }
    };

    float acc[2][8][4];
#pragma unroll
    for (int mt = 0; mt < 2; mt++)
#pragma unroll
        for (int nt = 0; nt < 8; nt++)
#pragma unroll
            for (int i = 0; i < 4; i++) acc[mt][nt][i] = 0.f;

    loadTile(0, 0);
    CP_COMMIT();

    for (int it = 0; it < kiters; ++it) {
        const int buf = it & 1;
        if (it + 1 < kiters) {
            loadTile(it + 1, buf ^ 1);
            CP_COMMIT();
            asm volatile("cp.async.wait_group 1;" ::: "memory");
        } else {
            asm volatile("cp.async.wait_group 0;" ::: "memory");
        }
        __syncthreads();

        const float* As = sm + aOff(buf);
        const float* Bs = sm + bOff(buf);
#pragma unroll
        for (int ks = 0; ks < 4; ks++) {
            const int ko = ks * 8;
            uint32_t a[2][4];
#pragma unroll
            for (int mt = 0; mt < 2; mt++) {
                int r0 = warpM * 32 + mt * 16 + g;
                a[mt][0] = f2tf32(As[r0 * SM_STRIDE + ko + t]);
                a[mt][1] = f2tf32(As[(r0 + 8) * SM_STRIDE + ko + t]);
                a[mt][2] = f2tf32(As[r0 * SM_STRIDE + ko + t + 4]);
                a[mt][3] = f2tf32(As[(r0 + 8) * SM_STRIDE + ko + t + 4]);
            }
            uint32_t b[8][2];
#pragma unroll
            for (int nt = 0; nt < 8; nt++) {
                int n = warpN * 64 + nt * 8 + g;
                b[nt][0] = f2tf32(Bs[n * SM_STRIDE + ko + t]);
                b[nt][1] = f2tf32(Bs[n * SM_STRIDE + ko + t + 4]);
            }
#pragma unroll
            for (int mt = 0; mt < 2; mt++)
#pragma unroll
                for (int nt = 0; nt < 8; nt++)
                    mma_tf32(acc[mt][nt], a[mt], b[nt]);
        }
        __syncthreads();
    }

    // ---- epilogue ----
#pragma unroll
    for (int mt = 0; mt < 2; mt++) {
#pragma unroll
        for (int sub = 0; sub < 2; sub++) {
            const int r = rowBase + warpM * 32 + mt * 16 + g + sub * 8;
#pragma unroll
            for (int nt = 0; nt < 8; nt++) {
                const int c = colBase + warpN * 64 + nt * 8 + 2 * t;
                float2 o;
                o.x = acc[mt][nt][sub * 2 + 0];
                o.y = acc[mt][nt][sub * 2 + 1];
                float2 bi = *(const float2*)&bias[c];
                o.x += bi.x; o.y += bi.y;
                if (res) {
                    float2 rr = *(const float2*)&res[(size_t)r * N + c];
                    o.x += rr.x; o.y += rr.y;
                }
                if (act == 1) {
                    o.x = (o.x > 0.f) ? (o.x + 1.f) : expf(o.x);
                    o.y = (o.y > 0.f) ? (o.y + 1.f) : expf(o.y);
                } else if (act == 2) {
                    o.x = fmaxf(o.x, 0.f);
                    o.y = fmaxf(o.y, 0.f);
                }
                *(float2*)&C[(size_t)r * N + c] = o;
            }
        }
    }
}

// ---------------- pad embeddings: [BS,586] -> [BS,608] (zero tail) ----------------
__global__ void pad_emb(const float* __restrict__ in, float* __restrict__ out) {
    int i = blockIdx.x * 256 + threadIdx.x;
    if (i >= BS * KPAD) return;
    int r = i / KPAD, c = i - r * KPAD;
    out[i] = (c < F_IN) ? in[(size_t)r * F_IN + c] : 0.f;
}

// ---------------- transpose with K padding: in[K,N] -> out[N,KP] ----------------
__global__ void transpose_pad(const float* __restrict__ in, float* __restrict__ out,
                              int K, int N, int KP) {
    __shared__ float t[32][33];
    int k0 = blockIdx.x * 32, n0 = blockIdx.y * 32;
    int x = threadIdx.x, y = threadIdx.y;
#pragma unroll
    for (int j = 0; j < 32; j += 8) {
        int kk = k0 + y + j;
        t[y + j][x] = (kk < K && n0 + x < N) ? in[(size_t)kk * N + n0 + x] : 0.f;
    }
    __syncthreads();
#pragma unroll
    for (int j = 0; j < 32; j += 8)
        if (n0 + y + j < N && k0 + x < KP)
            out[(size_t)(n0 + y + j) * KP + k0 + x] = t[x][y + j];
}

// ---------------- kv = sum_s k^T v (split-S, deterministic) ----------------
__global__ __launch_bounds__(256) void kv_kernel(
    const float* __restrict__ k, const float* __restrict__ v,
    float* __restrict__ kvpart, float* __restrict__ kspart)
{
    const int bh = blockIdx.x;
    const int b = bh >> 3, h = bh & 7;
    const int chunk = blockIdx.y;
    const int s0 = chunk * KV_CH;
    __shared__ float ksm[64][65];
    __shared__ float vsm[64][64];
    const int tid = threadIdx.x;
    const int m = tid & 63;
    const int dgrp = tid >> 6;
    float acc[16];
#pragma unroll
    for (int i = 0; i < 16; i++) acc[i] = 0.f;
    float kacc = 0.f;

    for (int c = 0; c < KV_CH; c += 64) {
#pragma unroll
        for (int i = 0; i < 16; i++) {
            int idx = tid + i * 256;
            int r = idx >> 6, cc = idx & 63;
            size_t gi = (size_t)(b * SEQ + s0 + c + r) * DM + h * HD + cc;
            ksm[r][cc] = k[gi];
            vsm[r][cc] = v[gi];
        }
        __syncthreads();
        for (int s = 0; s < 64; s++) {
            float vv = vsm[s][m];
#pragma unroll
            for (int i = 0; i < 16; i++)
                acc[i] = fmaf(ksm[s][dgrp * 16 + i], vv, acc[i]);
        }
        if (tid < 64) {
            float tt = 0.f;
            for (int s = 0; s < 64; s++) tt += ksm[s][tid];
            kacc += tt;
        }
        __syncthreads();
    }
#pragma unroll
    for (int i = 0; i < 16; i++) {
        int d = dgrp * 16 + i;
        kvpart[((size_t)(chunk * BH + bh) * HD + d) * HD + m] = acc[i];
    }
    if (tid < 64) kspart[(size_t)(chunk * BH + bh) * HD + tid] = kacc;
}

__global__ void reduce_kv(const float* __restrict__ part, float* __restrict__ kv) {
    int i = blockIdx.x * 256 + threadIdx.x;
    float a = 0.f;
#pragma unroll
    for (int c = 0; c < NCHUNK; c++) a += part[(size_t)c * (BH * HD * HD) + i];
    kv[i] = a;
}
__global__ void reduce_ks(const float* __restrict__ part, float* __restrict__ ks) {
    int i = blockIdx.x * 256 + threadIdx.x;
    float a = 0.f;
#pragma unroll
    for (int c = 0; c < NCHUNK; c++) a += part[(size_t)c * (BH * HD) + i];
    ks[i] = a;
}

// ---------------- attention apply ----------------
__global__ __launch_bounds__(256) void attn_kernel(
    const float* __restrict__ q, const float* __restrict__ kv,
    const float* __restrict__ ks, float* __restrict__ out)
{
    const int bh = blockIdx.x;
    const int b = bh >> 3, h = bh & 7;
    const int s0 = blockIdx.y * 64;
    __shared__ float kvsm[64][65];
    __shared__ float qsm[64][65];
    __shared__ float zsm[64];
    __shared__ float kssm[64];
    const int tid = threadIdx.x;
#pragma unroll
    for (int i = 0; i < 16; i++) {
        int idx = tid + i * 256;
        int d = idx >> 6, m = idx & 63;
        kvsm[d][m] = kv[((size_t)bh * HD + d) * HD + m];
        qsm[d][m] = q[(size_t)(b * SEQ + s0 + d) * DM + h * HD + m];
    }
    if (tid < 64) kssm[tid] = ks[bh * HD + tid];
    __syncthreads();
    if (tid < 64) {
        float a = 0.f;
        for (int d = 0; d < 64; d++) a = fmaf(qsm[tid][d], kssm[d], a);
        zsm[tid] = 1.f / (a + EPS_ATTN);
    }
    __syncthreads();
    const int m = tid & 63;
    const int tgrp = tid >> 6;
#pragma unroll
    for (int i = 0; i < 16; i++) {
        int tt = tgrp * 16 + i;
        float a = 0.f;
#pragma unroll
        for (int d = 0; d < 64; d++) a = fmaf(qsm[tt][d], kvsm[d][m], a);
        out[(size_t)(b * SEQ + s0 + tt) * DM + h * HD + m] = a * zsm[tt];
    }
}

// ---------------- block reduce helper ----------------
__device__ __forceinline__ float bsum128(float v, float* sm) {
#pragma unroll
    for (int o = 16; o > 0; o >>= 1) v += __shfl_down_sync(0xffffffffu, v, o);
    int w = threadIdx.x >> 5;
    if ((threadIdx.x & 31) == 0) sm[w] = v;
    __syncthreads();
    float r = sm[0] + sm[1] + sm[2] + sm[3];
    __syncthreads();
    return r;
}

// ---------------- layernorm ----------------
__global__ __launch_bounds__(128) void ln_kernel(
    const float* __restrict__ in, const float* __restrict__ g,
    const float* __restrict__ b, float* __restrict__ out)
{
    __shared__ float sm[4];
    const int row = blockIdx.x;
    const int tid = threadIdx.x;
    float4 v = ((const float4*)(in + (size_t)row * DM))[tid];
    float s  = v.x + v.y + v.z + v.w;
    float sq = v.x * v.x + v.y * v.y + v.z * v.z + v.w * v.w;
    s  = bsum128(s, sm);
    sq = bsum128(sq, sm);
    float mu = s * (1.f / DM);
    float var = sq * (1.f / DM) - mu * mu;
    float rstd = rsqrtf(var + EPS_LN);
    float4 gg = ((const float4*)g)[tid];
    float4 bb = ((const float4*)b)[tid];
    float4 o;
    o.x = (v.x - mu) * rstd * gg.x + bb.x;
    o.y = (v.y - mu) * rstd * gg.y + bb.y;
    o.z = (v.z - mu) * rstd * gg.z + bb.z;
    o.w = (v.w - mu) * rstd * gg.w + bb.w;
    ((float4*)(out + (size_t)row * DM))[tid] = o;
}

// ---------------- fused final LN + out proj ----------------
__global__ __launch_bounds__(128) void final_kernel(
    const float* __restrict__ in, const float* __restrict__ g,
    const float* __restrict__ b, const float* __restrict__ w,
    const float* __restrict__ bout, float* __restrict__ out)
{
    __shared__ float sm[4];
    const int row = blockIdx.x;
    const int tid = threadIdx.x;
    float4 v = ((const float4*)(in + (size_t)row * DM))[tid];
    float s  = v.x + v.y + v.z + v.w;
    float sq = v.x * v.x + v.y * v.y + v.z * v.z + v.w * v.w;
    s  = bsum128(s, sm);
    sq = bsum128(sq, sm);
    float mu = s * (1.f / DM);
    float var = sq * (1.f / DM) - mu * mu;
    float rstd = rsqrtf(var + EPS_LN);
    float4 gg = ((const float4*)g)[tid];
    float4 bb = ((const float4*)b)[tid];
    float4 ww = ((const float4*)w)[tid];
    float acc = ((v.x - mu) * rstd * gg.x + bb.x) * ww.x
              + ((v.y - mu) * rstd * gg.y + bb.y) * ww.y
              + ((v.z - mu) * rstd * gg.z + bb.z) * ww.z
              + ((v.w - mu) * rstd * gg.w + bb.w) * ww.w;
    acc = bsum128(acc, sm);
    if (tid == 0) out[row] = acc + bout[0];
}

// ---------------- launch helpers ----------------
static inline void launch_gemm(const float* A, const float* BT, const float* bias,
                               const float* res, float* C, int M, int N, int K, int act) {
    dim3 grid(N / GBN, M / GBM);
    gemm_tc<<<grid, 256, GEMM_SMEM>>>(A, BT, bias, res, C, M, N, K, act);
}
static inline void launch_transpose(const float* in, float* out, int K, int N, int KP) {
    dim3 grid((KP + 31) / 32, (N + 31) / 32);
    transpose_pad<<<grid, dim3(32, 8)>>>(in, out, K, N, KP);
}

extern "C" void kernel_launch(void* const* d_in, const int* in_sizes, int n_in,
                              void* d_out, int out_size)
{
    const float* emb   = (const float*)d_in[0];
    const float* W0    = (const float*)d_in[1];
    const float* b0    = (const float*)d_in[2];
    const float* Wq    = (const float*)d_in[3];
    const float* bq    = (const float*)d_in[4];
    const float* Wk    = (const float*)d_in[5];
    const float* bk    = (const float*)d_in[6];
    const float* Wv    = (const float*)d_in[7];
    const float* bv    = (const float*)d_in[8];
    const float* Wo    = (const float*)d_in[9];
    const float* bo    = (const float*)d_in[10];
    const float* ln1s  = (const float*)d_in[11];
    const float* ln1b  = (const float*)d_in[12];
    const float* W1    = (const float*)d_in[13];
    const float* b1    = (const float*)d_in[14];
    const float* W2    = (const float*)d_in[15];
    const float* b2    = (const float*)d_in[16];
    const float* ln2s  = (const float*)d_in[17];
    const float* ln2b  = (const float*)d_in[18];
    const float* lnfs  = (const float*)d_in[19];
    const float* lnfb  = (const float*)d_in[20];
    const float* Wout  = (const float*)d_in[21];
    const float* bout  = (const float*)d_in[22];
    float* out = (float*)d_out;

    cudaFuncSetAttribute(gemm_tc, cudaFuncAttributeMaxDynamicSharedMemorySize, GEMM_SMEM);

    float *pe, *px, *pq, *pk, *pv, *pt, *ph, *pkvp, *pksp, *pkv, *pks;
    float *w0t, *wqt, *wkt, *wvt, *wot, *w1t, *w2t;
    cudaGetSymbolAddress((void**)&pe,  g_e);
    cudaGetSymbolAddress((void**)&px,  g_x);
    cudaGetSymbolAddress((void**)&pq,  g_q);
    cudaGetSymbolAddress((void**)&pk,  g_k);
    cudaGetSymbolAddress((void**)&pv,  g_v);
    cudaGetSymbolAddress((void**)&pt,  g_t);
    cudaGetSymbolAddress((void**)&ph,  g_h);
    cudaGetSymbolAddress((void**)&pkvp, g_kvpart);
    cudaGetSymbolAddress((void**)&pksp, g_kspart);
    cudaGetSymbolAddress((void**)&pkv, g_kv);
    cudaGetSymbolAddress((void**)&pks, g_ks);
    cudaGetSymbolAddress((void**)&w0t, g_w0t);
    cudaGetSymbolAddress((void**)&wqt, g_wqt);
    cudaGetSymbolAddress((void**)&wkt, g_wkt);
    cudaGetSymbolAddress((void**)&wvt, g_wvt);
    cudaGetSymbolAddress((void**)&wot, g_wot);
    cudaGetSymbolAddress((void**)&w1t, g_w1t);
    cudaGetSymbolAddress((void**)&w2t, g_w2t);

    // pad embeddings + transpose all weights to [N,K]
    pad_emb<<<(BS * KPAD + 255) / 256, 256>>>(emb, pe);
    launch_transpose(W0, w0t, F_IN, DM, KPAD);
    for (int l = 0; l < NLAY; l++) {
        launch_transpose(Wq + (size_t)l * DM * DM, wqt + (size_t)l * DM * DM, DM, DM, DM);
        launch_transpose(Wk + (size_t)l * DM * DM, wkt + (size_t)l * DM * DM, DM, DM, DM);
        launch_transpose(Wv + (size_t)l * DM * DM, wvt + (size_t)l * DM * DM, DM, DM, DM);
        launch_transpose(Wo + (size_t)l * DM * DM, wot + (size_t)l * DM * DM, DM, DM, DM);
        launch_transpose(W1 + (size_t)l * DM * FF, w1t + (size_t)l * DM * FF, DM, FF, DM);
        launch_transpose(W2 + (size_t)l * FF * DM, w2t + (size_t)l * FF * DM, FF, DM, FF);
    }

    // input projection (K padded to 608)
    launch_gemm(pe, w0t, b0, nullptr, px, BS, DM, KPAD, 0);

    for (int l = 0; l < NLAY; l++) {
        const float* wqt_l = wqt + (size_t)l * DM * DM;
        const float* wkt_l = wkt + (size_t)l * DM * DM;
        const float* wvt_l = wvt + (size_t)l * DM * DM;
        const float* wot_l = wot + (size_t)l * DM * DM;
        const float* w1t_l = w1t + (size_t)l * DM * FF;
        const float* w2t_l = w2t + (size_t)l * FF * DM;
        const float* bq_l = bq + (size_t)l * DM;
        const float* bk_l = bk + (size_t)l * DM;
        const float* bv_l = bv + (size_t)l * DM;
        const float* bo_l = bo + (size_t)l * DM;
        const float* b1_l = b1 + (size_t)l * FF;
        const float* b2_l = b2 + (size_t)l * DM;

        launch_gemm(px, wqt_l, bq_l, nullptr, pq, BS, DM, DM, 1);   // elu+1
        launch_gemm(px, wkt_l, bk_l, nullptr, pk, BS, DM, DM, 1);   // elu+1
        launch_gemm(px, wvt_l, bv_l, nullptr, pv, BS, DM, DM, 0);

        kv_kernel<<<dim3(BH, NCHUNK), 256>>>(pk, pv, pkvp, pksp);
        reduce_kv<<<(BH * HD * HD) / 256, 256>>>(pkvp, pkv);
        reduce_ks<<<(BH * HD) / 256, 256>>>(pksp, pks);
        attn_kernel<<<dim3(BH, SEQ / 64), 256>>>(pq, pkv, pks, pt);

        launch_gemm(pt, wot_l, bo_l, px, pq, BS, DM, DM, 0);
        ln_kernel<<<BS, 128>>>(pq, ln1s + (size_t)l * DM, ln1b + (size_t)l * DM, px);

        launch_gemm(px, w1t_l, b1_l, nullptr, ph, BS, FF, DM, 2);   // relu
        launch_gemm(ph, w2t_l, b2_l, px, pq, BS, DM, FF, 0);
        ln_kernel<<<BS, 128>>>(pq, ln2s + (size_t)l * DM, ln2b + (size_t)l * DM, px);
    }

    final_kernel<<<BS, 128>>>(px, lnfs, lnfb, Wout, bout, out);
}

// round 6
// speedup vs baseline: 6.0087x; 1.6087x over previous
#include <cuda_runtime.h>
#include <cuda_fp16.h>
#include <math.h>
#include <stdint.h>

// ---------------- problem constants ----------------
#define BATCH 8
#define SEQ   4096
#define F_IN  586
#define KPAD  640            // F_IN padded to multiple of 64 (fp16 BK tile)
#define DM    512
#define NH    8
#define HD    64
#define FF    1024
#define NLAY  2
#define BS    (BATCH*SEQ) // 32768
#define BH    (BATCH*NH)  // 64
#define EPS_ATTN 1e-6f
#define EPS_LN   1e-5f

// ---------------- scratch (device globals) ----------------
__device__ __half g_he[BS*KPAD];     // fp16 padded embeddings
__device__ __half g_hx[BS*DM];       // fp16 copy of x (GEMM A operand)
__device__ __half g_ht[BS*DM];       // fp16 attention output
__device__ __half g_hh[BS*FF];       // fp16 FFN hidden
__device__ float  g_x [BS*DM];       // f32 x (residual / LN)
__device__ float  g_q [BS*DM];       // f32 q, reused as gemm out
__device__ float  g_k [BS*DM];
__device__ float  g_v [BS*DM];
#define NCHUNK 8
#define KV_CH  (SEQ/NCHUNK)
__device__ float g_kvpart[NCHUNK*BH*HD*HD];
__device__ float g_kspart[NCHUNK*BH*HD];
__device__ float g_kv[BH*HD*HD];
__device__ float g_ks[BH*HD];
// fp16 transposed weights [N,K]
__device__ __half g_w0t[DM*KPAD];
__device__ __half g_wqt[NLAY*DM*DM];
__device__ __half g_wkt[NLAY*DM*DM];
__device__ __half g_wvt[NLAY*DM*DM];
__device__ __half g_wot[NLAY*DM*DM];
__device__ __half g_w1t[NLAY*FF*DM];
__device__ __half g_w2t[NLAY*DM*FF];

// ---------------- helpers ----------------
__device__ __forceinline__ uint32_t smem_u32(const void* p) {
    uint32_t a;
    asm("{ .reg .u64 t; cvta.to.shared.u64 t, %1; cvt.u32.u64 %0, t; }" : "=r"(a) : "l"(p));
    return a;
}
__device__ __forceinline__ void cp_async16(uint32_t dst, const void* src) {
    asm volatile("cp.async.cg.shared.global [%0], [%1], 16;"
                 :: "r"(dst), "l"(src) : "memory");
}
#define CP_COMMIT() asm volatile("cp.async.commit_group;" ::: "memory")

__device__ __forceinline__ void ldmatrix_x4(uint32_t* r, uint32_t addr) {
    asm volatile("ldmatrix.sync.aligned.m8n8.x4.shared.b16 {%0,%1,%2,%3}, [%4];"
                 : "=r"(r[0]), "=r"(r[1]), "=r"(r[2]), "=r"(r[3]) : "r"(addr));
}
__device__ __forceinline__ void mma_f16(float* c, const uint32_t* a, uint32_t b0, uint32_t b1) {
    asm volatile(
        "mma.sync.aligned.m16n8k16.row.col.f32.f16.f16.f32 "
        "{%0,%1,%2,%3}, {%4,%5,%6,%7}, {%8,%9}, {%0,%1,%2,%3};"
        : "+f"(c[0]), "+f"(c[1]), "+f"(c[2]), "+f"(c[3])
        : "r"(a[0]), "r"(a[1]), "r"(a[2]), "r"(a[3]), "r"(b0), "r"(b1));
}

// ---------------- fp16 tensor-core GEMM ----------------
// Cf/Ch[M,N] = act(A[M,K] @ BT[N,K]^T + bias (+res)); K multiple of 64.
// act: 0 none, 1 elu+1, 2 relu. Cf (f32) and Ch (fp16) each optional.
#define GBM 128
#define GBN 128
#define HBK 64                        // halves per K tile (128 bytes/row)
#define TILE_B 16384                  // bytes per tile buffer
#define GEMM_SMEM (4*TILE_B)          // A0 A1 B0 B1 = 64 KB

__global__ __launch_bounds__(256) void gemm_h(
    const __half* __restrict__ A, const __half* __restrict__ BT,
    const float* __restrict__ bias, const float* __restrict__ res,
    float* __restrict__ Cf, __half* __restrict__ Ch,
    int M, int N, int K, int act)
{
    extern __shared__ char smraw[];
    const uint32_t smBase = smem_u32(smraw);
    const int tid  = threadIdx.x;
    const int warp = tid >> 5;
    const int lane = tid & 31;
    const int g = lane >> 2;
    const int t = lane & 3;
    const int warpM = warp & 3;       // 0..3 (32-row strip)
    const int warpN = warp >> 2;      // 0..1 (64-col strip)
    const int rowBase = blockIdx.y * GBM;
    const int colBase = blockIdx.x * GBN;
    const int kiters = K / HBK;

    auto loadTile = [&](int it, int buf) {
        const int k0 = it * HBK;
#pragma unroll
        for (int p = 0; p < 4; p++) {
            int idx = tid + p * 256;
            int row = idx >> 3, c = idx & 7;
            uint32_t dst = smBase + buf * TILE_B + row * 128 + ((c ^ (row & 7)) << 4);
            cp_async16(dst, &A[(size_t)(rowBase + row) * K + k0 + c * 8]);
        }
#pragma unroll
        for (int p = 0; p < 4; p++) {
            int idx = tid + p * 256;
            int row = idx >> 3, c = idx & 7;
            uint32_t dst = smBase + 2 * TILE_B + buf * TILE_B + row * 128 + ((c ^ (row & 7)) << 4);
            cp_async16(dst, &BT[(size_t)(colBase + row) * K + k0 + c * 8]);
        }
    };

    float acc[2][8][4];
#pragma unroll
    for (int mt = 0; mt < 2; mt++)
#pragma unroll
        for (int nt = 0; nt < 8; nt++)
#pragma unroll
            for (int i = 0; i < 4; i++) acc[mt][nt][i] = 0.f;

    loadTile(0, 0);
    CP_COMMIT();

    for (int it = 0; it < kiters; ++it) {
        const int buf = it & 1;
        if (it + 1 < kiters) {
            loadTile(it + 1, buf ^ 1);
            CP_COMMIT();
            asm volatile("cp.async.wait_group 1;" ::: "memory");
        } else {
            asm volatile("cp.async.wait_group 0;" ::: "memory");
        }
        __syncthreads();

        const uint32_t Abase = smBase + buf * TILE_B;
        const uint32_t Bbase = smBase + 2 * TILE_B + buf * TILE_B;
        const int lrow = lane & 15;   // row within 16-row ldmatrix tile
        const int khalf = lane >> 4;  // 0/1 -> k chunk select
#pragma unroll
        for (int ks = 0; ks < 4; ks++) {
            const int cIdx = 2 * ks + khalf;
            uint32_t a[2][4];
#pragma unroll
            for (int mt = 0; mt < 2; mt++) {
                int row = warpM * 32 + mt * 16 + lrow;
                ldmatrix_x4(a[mt], Abase + row * 128 + ((cIdx ^ (row & 7)) << 4));
            }
            uint32_t br[4][4];
#pragma unroll
            for (int j = 0; j < 4; j++) {
                int row = warpN * 64 + j * 16 + lrow;
                ldmatrix_x4(br[j], Bbase + row * 128 + ((cIdx ^ (row & 7)) << 4));
            }
#pragma unroll
            for (int mt = 0; mt < 2; mt++)
#pragma unroll
                for (int j = 0; j < 4; j++) {
                    mma_f16(acc[mt][2 * j],     a[mt], br[j][0], br[j][2]);
                    mma_f16(acc[mt][2 * j + 1], a[mt], br[j][1], br[j][3]);
                }
        }
        __syncthreads();
    }

    // ---- epilogue ----
#pragma unroll
    for (int mt = 0; mt < 2; mt++) {
#pragma unroll
        for (int sub = 0; sub < 2; sub++) {
            const int r = rowBase + warpM * 32 + mt * 16 + g + sub * 8;
#pragma unroll
            for (int nt = 0; nt < 8; nt++) {
                const int c = colBase + warpN * 64 + nt * 8 + 2 * t;
                float2 o;
                o.x = acc[mt][nt][sub * 2 + 0];
                o.y = acc[mt][nt][sub * 2 + 1];
                float2 bi = *(const float2*)&bias[c];
                o.x += bi.x; o.y += bi.y;
                if (res) {
                    float2 rr = *(const float2*)&res[(size_t)r * N + c];
                    o.x += rr.x; o.y += rr.y;
                }
                if (act == 1) {
                    o.x = (o.x > 0.f) ? (o.x + 1.f) : expf(o.x);
                    o.y = (o.y > 0.f) ? (o.y + 1.f) : expf(o.y);
                } else if (act == 2) {
                    o.x = fmaxf(o.x, 0.f);
                    o.y = fmaxf(o.y, 0.f);
                }
                if (Cf) *(float2*)&Cf[(size_t)r * N + c] = o;
                if (Ch) *(__half2*)&Ch[(size_t)r * N + c] = __floats2half2_rn(o.x, o.y);
            }
        }
    }
}

// ---------------- pad embeddings: [BS,586] f32 -> [BS,640] fp16 ----------------
__global__ void pad_emb_h(const float* __restrict__ in, __half* __restrict__ out) {
    int i = blockIdx.x * 256 + threadIdx.x;
    if (i >= BS * KPAD) return;
    int r = i / KPAD, c = i - r * KPAD;
    out[i] = (c < F_IN) ? __float2half(in[(size_t)r * F_IN + c]) : __half(0.f);
}

// ---------------- transpose+pad+quantize: f32 in[K,N] -> fp16 out[N,KP] ----------------
__global__ void transpose_pad_h(const float* __restrict__ in, __half* __restrict__ out,
                                int K, int N, int KP) {
    __shared__ float t[32][33];
    int k0 = blockIdx.x * 32, n0 = blockIdx.y * 32;
    int x = threadIdx.x, y = threadIdx.y;
#pragma unroll
    for (int j = 0; j < 32; j += 8) {
        int kk = k0 + y + j;
        t[y + j][x] = (kk < K && n0 + x < N) ? in[(size_t)kk * N + n0 + x] : 0.f;
    }
    __syncthreads();
#pragma unroll
    for (int j = 0; j < 32; j += 8)
        if (n0 + y + j < N && k0 + x < KP)
            out[(size_t)(n0 + y + j) * KP + k0 + x] = __float2half(t[x][y + j]);
}

// ---------------- kv = sum_s k^T v (split-S, deterministic) ----------------
__global__ __launch_bounds__(256) void kv_kernel(
    const float* __restrict__ k, const float* __restrict__ v,
    float* __restrict__ kvpart, float* __restrict__ kspart)
{
    const int bh = blockIdx.x;
    const int b = bh >> 3, h = bh & 7;
    const int chunk = blockIdx.y;
    const int s0 = chunk * KV_CH;
    __shared__ float ksm[64][65];
    __shared__ float vsm[64][64];
    const int tid = threadIdx.x;
    const int m = tid & 63;
    const int dgrp = tid >> 6;
    float acc[16];
#pragma unroll
    for (int i = 0; i < 16; i++) acc[i] = 0.f;
    float kacc = 0.f;

    for (int c = 0; c < KV_CH; c += 64) {
#pragma unroll
        for (int i = 0; i < 16; i++) {
            int idx = tid + i * 256;
            int r = idx >> 6, cc = idx & 63;
            size_t gi = (size_t)(b * SEQ + s0 + c + r) * DM + h * HD + cc;
            ksm[r][cc] = k[gi];
            vsm[r][cc] = v[gi];
        }
        __syncthreads();
        for (int s = 0; s < 64; s++) {
            float vv = vsm[s][m];
#pragma unroll
            for (int i = 0; i < 16; i++)
                acc[i] = fmaf(ksm[s][dgrp * 16 + i], vv, acc[i]);
        }
        if (tid < 64) {
            float tt = 0.f;
            for (int s = 0; s < 64; s++) tt += ksm[s][tid];
            kacc += tt;
        }
        __syncthreads();
    }
#pragma unroll
    for (int i = 0; i < 16; i++) {
        int d = dgrp * 16 + i;
        kvpart[((size_t)(chunk * BH + bh) * HD + d) * HD + m] = acc[i];
    }
    if (tid < 64) kspart[(size_t)(chunk * BH + bh) * HD + tid] = kacc;
}

__global__ void reduce_kv(const float* __restrict__ part, float* __restrict__ kv) {
    int i = blockIdx.x * 256 + threadIdx.x;
    float a = 0.f;
#pragma unroll
    for (int c = 0; c < NCHUNK; c++) a += part[(size_t)c * (BH * HD * HD) + i];
    kv[i] = a;
}
__global__ void reduce_ks(const float* __restrict__ part, float* __restrict__ ks) {
    int i = blockIdx.x * 256 + threadIdx.x;
    float a = 0.f;
#pragma unroll
    for (int c = 0; c < NCHUNK; c++) a += part[(size_t)c * (BH * HD) + i];
    ks[i] = a;
}

// ---------------- attention apply (writes fp16 for the Wo GEMM) ----------------
__global__ __launch_bounds__(256) void attn_kernel(
    const float* __restrict__ q, const float* __restrict__ kv,
    const float* __restrict__ ks, __half* __restrict__ out)
{
    const int bh = blockIdx.x;
    const int b = bh >> 3, h = bh & 7;
    const int s0 = blockIdx.y * 64;
    __shared__ float kvsm[64][65];
    __shared__ float qsm[64][65];
    __shared__ float zsm[64];
    __shared__ float kssm[64];
    const int tid = threadIdx.x;
#pragma unroll
    for (int i = 0; i < 16; i++) {
        int idx = tid + i * 256;
        int d = idx >> 6, m = idx & 63;
        kvsm[d][m] = kv[((size_t)bh * HD + d) * HD + m];
        qsm[d][m] = q[(size_t)(b * SEQ + s0 + d) * DM + h * HD + m];
    }
    if (tid < 64) kssm[tid] = ks[bh * HD + tid];
    __syncthreads();
    if (tid < 64) {
        float a = 0.f;
        for (int d = 0; d < 64; d++) a = fmaf(qsm[tid][d], kssm[d], a);
        zsm[tid] = 1.f / (a + EPS_ATTN);
    }
    __syncthreads();
    const int m = tid & 63;
    const int tgrp = tid >> 6;
#pragma unroll
    for (int i = 0; i < 16; i++) {
        int tt = tgrp * 16 + i;
        float a = 0.f;
#pragma unroll
        for (int d = 0; d < 64; d++) a = fmaf(qsm[tt][d], kvsm[d][m], a);
        out[(size_t)(b * SEQ + s0 + tt) * DM + h * HD + m] = __float2half(a * zsm[tt]);
    }
}

// ---------------- block reduce helper ----------------
__device__ __forceinline__ float bsum128(float v, float* sm) {
#pragma unroll
    for (int o = 16; o > 0; o >>= 1) v += __shfl_down_sync(0xffffffffu, v, o);
    int w = threadIdx.x >> 5;
    if ((threadIdx.x & 31) == 0) sm[w] = v;
    __syncthreads();
    float r = sm[0] + sm[1] + sm[2] + sm[3];
    __syncthreads();
    return r;
}

// ---------------- layernorm: f32 out + fp16 copy ----------------
__global__ __launch_bounds__(128) void ln_kernel(
    const float* __restrict__ in, const float* __restrict__ g,
    const float* __restrict__ b, float* __restrict__ out,
    __half* __restrict__ hout)
{
    __shared__ float sm[4];
    const int row = blockIdx.x;
    const int tid = threadIdx.x;
    float4 v = ((const float4*)(in + (size_t)row * DM))[tid];
    float s  = v.x + v.y + v.z + v.w;
    float sq = v.x * v.x + v.y * v.y + v.z * v.z + v.w * v.w;
    s  = bsum128(s, sm);
    sq = bsum128(sq, sm);
    float mu = s * (1.f / DM);
    float var = sq * (1.f / DM) - mu * mu;
    float rstd = rsqrtf(var + EPS_LN);
    float4 gg = ((const float4*)g)[tid];
    float4 bb = ((const float4*)b)[tid];
    float4 o;
    o.x = (v.x - mu) * rstd * gg.x + bb.x;
    o.y = (v.y - mu) * rstd * gg.y + bb.y;
    o.z = (v.z - mu) * rstd * gg.z + bb.z;
    o.w = (v.w - mu) * rstd * gg.w + bb.w;
    ((float4*)(out + (size_t)row * DM))[tid] = o;
    __half2 h0 = __floats2half2_rn(o.x, o.y);
    __half2 h1 = __floats2half2_rn(o.z, o.w);
    ((__half2*)(hout + (size_t)row * DM))[tid * 2 + 0] = h0;
    ((__half2*)(hout + (size_t)row * DM))[tid * 2 + 1] = h1;
}

// ---------------- fused final LN + out proj ----------------
__global__ __launch_bounds__(128) void final_kernel(
    const float* __restrict__ in, const float* __restrict__ g,
    const float* __restrict__ b, const float* __restrict__ w,
    const float* __restrict__ bout, float* __restrict__ out)
{
    __shared__ float sm[4];
    const int row = blockIdx.x;
    const int tid = threadIdx.x;
    float4 v = ((const float4*)(in + (size_t)row * DM))[tid];
    float s  = v.x + v.y + v.z + v.w;
    float sq = v.x * v.x + v.y * v.y + v.z * v.z + v.w * v.w;
    s  = bsum128(s, sm);
    sq = bsum128(sq, sm);
    float mu = s * (1.f / DM);
    float var = sq * (1.f / DM) - mu * mu;
    float rstd = rsqrtf(var + EPS_LN);
    float4 gg = ((const float4*)g)[tid];
    float4 bb = ((const float4*)b)[tid];
    float4 ww = ((const float4*)w)[tid];
    float acc = ((v.x - mu) * rstd * gg.x + bb.x) * ww.x
              + ((v.y - mu) * rstd * gg.y + bb.y) * ww.y
              + ((v.z - mu) * rstd * gg.z + bb.z) * ww.z
              + ((v.w - mu) * rstd * gg.w + bb.w) * ww.w;
    acc = bsum128(acc, sm);
    if (tid == 0) out[row] = acc + bout[0];
}

// ---------------- launch helpers ----------------
static inline void launch_gemm(const __half* A, const __half* BT, const float* bias,
                               const float* res, float* Cf, __half* Ch,
                               int M, int N, int K, int act) {
    dim3 grid(N / GBN, M / GBM);
    gemm_h<<<grid, 256, GEMM_SMEM>>>(A, BT, bias, res, Cf, Ch, M, N, K, act);
}
static inline void launch_transpose(const float* in, __half* out, int K, int N, int KP) {
    dim3 grid((KP + 31) / 32, (N + 31) / 32);
    transpose_pad_h<<<grid, dim3(32, 8)>>>(in, out, K, N, KP);
}

extern "C" void kernel_launch(void* const* d_in, const int* in_sizes, int n_in,
                              void* d_out, int out_size)
{
    const float* emb   = (const float*)d_in[0];
    const float* W0    = (const float*)d_in[1];
    const float* b0    = (const float*)d_in[2];
    const float* Wq    = (const float*)d_in[3];
    const float* bq    = (const float*)d_in[4];
    const float* Wk    = (const float*)d_in[5];
    const float* bk    = (const float*)d_in[6];
    const float* Wv    = (const float*)d_in[7];
    const float* bv    = (const float*)d_in[8];
    const float* Wo    = (const float*)d_in[9];
    const float* bo    = (const float*)d_in[10];
    const float* ln1s  = (const float*)d_in[11];
    const float* ln1b  = (const float*)d_in[12];
    const float* W1    = (const float*)d_in[13];
    const float* b1    = (const float*)d_in[14];
    const float* W2    = (const float*)d_in[15];
    const float* b2    = (const float*)d_in[16];
    const float* ln2s  = (const float*)d_in[17];
    const float* ln2b  = (const float*)d_in[18];
    const float* lnfs  = (const float*)d_in[19];
    const float* lnfb  = (const float*)d_in[20];
    const float* Wout  = (const float*)d_in[21];
    const float* bout  = (const float*)d_in[22];
    float* out = (float*)d_out;

    cudaFuncSetAttribute(gemm_h, cudaFuncAttributeMaxDynamicSharedMemorySize, GEMM_SMEM);

    __half *he, *hx, *ht, *hh;
    __half *w0t, *wqt, *wkt, *wvt, *wot, *w1t, *w2t;
    float *px, *pq, *pk, *pv, *pkvp, *pksp, *pkv, *pks;
    cudaGetSymbolAddress((void**)&he,  g_he);
    cudaGetSymbolAddress((void**)&hx,  g_hx);
    cudaGetSymbolAddress((void**)&ht,  g_ht);
    cudaGetSymbolAddress((void**)&hh,  g_hh);
    cudaGetSymbolAddress((void**)&px,  g_x);
    cudaGetSymbolAddress((void**)&pq,  g_q);
    cudaGetSymbolAddress((void**)&pk,  g_k);
    cudaGetSymbolAddress((void**)&pv,  g_v);
    cudaGetSymbolAddress((void**)&pkvp, g_kvpart);
    cudaGetSymbolAddress((void**)&pksp, g_kspart);
    cudaGetSymbolAddress((void**)&pkv, g_kv);
    cudaGetSymbolAddress((void**)&pks, g_ks);
    cudaGetSymbolAddress((void**)&w0t, g_w0t);
    cudaGetSymbolAddress((void**)&wqt, g_wqt);
    cudaGetSymbolAddress((void**)&wkt, g_wkt);
    cudaGetSymbolAddress((void**)&wvt, g_wvt);
    cudaGetSymbolAddress((void**)&wot, g_wot);
    cudaGetSymbolAddress((void**)&w1t, g_w1t);
    cudaGetSymbolAddress((void**)&w2t, g_w2t);

    // prep: pad/quantize embeddings; transpose+quantize weights to fp16 [N,K]
    pad_emb_h<<<(BS * KPAD + 255) / 256, 256>>>(emb, he);
    launch_transpose(W0, w0t, F_IN, DM, KPAD);
    for (int l = 0; l < NLAY; l++) {
        launch_transpose(Wq + (size_t)l * DM * DM, wqt + (size_t)l * DM * DM, DM, DM, DM);
        launch_transpose(Wk + (size_t)l * DM * DM, wkt + (size_t)l * DM * DM, DM, DM, DM);
        launch_transpose(Wv + (size_t)l * DM * DM, wvt + (size_t)l * DM * DM, DM, DM, DM);
        launch_transpose(Wo + (size_t)l * DM * DM, wot + (size_t)l * DM * DM, DM, DM, DM);
        launch_transpose(W1 + (size_t)l * DM * FF, w1t + (size_t)l * DM * FF, DM, FF, DM);
        launch_transpose(W2 + (size_t)l * FF * DM, w2t + (size_t)l * FF * DM, FF, DM, FF);
    }

    // input projection: x0 (f32 + fp16 copy)
    launch_gemm(he, w0t, b0, nullptr, px, hx, BS, DM, KPAD, 0);

    for (int l = 0; l < NLAY; l++) {
        const __half* wqt_l = wqt + (size_t)l * DM * DM;
        const __half* wkt_l = wkt + (size_t)l * DM * DM;
        const __half* wvt_l = wvt + (size_t)l * DM * DM;
        const __half* wot_l = wot + (size_t)l * DM * DM;
        const __half* w1t_l = w1t + (size_t)l * DM * FF;
        const __half* w2t_l = w2t + (size_t)l * FF * DM;
        const float* bq_l = bq + (size_t)l * DM;
        const float* bk_l = bk + (size_t)l * DM;
        const float* bv_l = bv + (size_t)l * DM;
        const float* bo_l = bo + (size_t)l * DM;
        const float* b1_l = b1 + (size_t)l * FF;
        const float* b2_l = b2 + (size_t)l * DM;

        launch_gemm(hx, wqt_l, bq_l, nullptr, pq, nullptr, BS, DM, DM, 1);   // q = elu+1
        launch_gemm(hx, wkt_l, bk_l, nullptr, pk, nullptr, BS, DM, DM, 1);   // k = elu+1
        launch_gemm(hx, wvt_l, bv_l, nullptr, pv, nullptr, BS, DM, DM, 0);   // v

        kv_kernel<<<dim3(BH, NCHUNK), 256>>>(pk, pv, pkvp, pksp);
        reduce_kv<<<(BH * HD * HD) / 256, 256>>>(pkvp, pkv);
        reduce_ks<<<(BH * HD) / 256, 256>>>(pksp, pks);
        attn_kernel<<<dim3(BH, SEQ / 64), 256>>>(pq, pkv, pks, ht);

        // out proj + residual -> pq (f32); LN -> px (f32) + hx (fp16)
        launch_gemm(ht, wot_l, bo_l, px, pq, nullptr, BS, DM, DM, 0);
        ln_kernel<<<BS, 128>>>(pq, ln1s + (size_t)l * DM, ln1b + (size_t)l * DM, px, hx);

        // FFN
        launch_gemm(hx, w1t_l, b1_l, nullptr, nullptr, hh, BS, FF, DM, 2);   // relu, fp16 only
        launch_gemm(hh, w2t_l, b2_l, px, pq, nullptr, BS, DM, FF, 0);
        ln_kernel<<<BS, 128>>>(pq, ln2s + (size_t)l * DM, ln2b + (size_t)l * DM, px, hx);
    }

    final_kernel<<<BS, 128>>>(px, lnfs, lnfb, Wout, bout, out);
}